// round 11
// baseline (speedup 1.0000x reference)
#include <cuda_runtime.h>
#include <cuda_fp16.h>
#include <cstdint>

#define IN_F     4096
#define OUT_F    4096
#define N_TOK    8192
#define GROUP    128
#define NGROUPS  (IN_F / GROUP)
#define N_STAGES 4
#define QMAXF    15.0f

// ---------------- scratch (device globals; no runtime allocation) ----------
__device__ __half g_w_h[(size_t)OUT_F * IN_F];
__device__ __half g_x_h[(size_t)N_TOK * IN_F];

// ---------------------------------------------------------------------------
// Kernel 1: fused weight transform + x->fp16 conversion (unchanged from R10).
// ---------------------------------------------------------------------------
#define ROWS_PB 64
#define WPAD    132
#define TBLOCKS (NGROUPS * (OUT_F / ROWS_PB))          // 2048
#define XCHUNK  ((size_t)N_TOK * IN_F / TBLOCKS)       // 16384 elems / block

__global__ __launch_bounds__(256) void transform_kernel(
    const float* __restrict__ weight,
    const float* __restrict__ channel_scales,
    const float* __restrict__ theta,
    const float* __restrict__ q_scale,
    const float* __restrict__ q_zp,
    const int*   __restrict__ pairs,
    const float* __restrict__ x)
{
    const int g    = blockIdx.x;
    const int row0 = blockIdx.y * ROWS_PB;
    const int tid  = threadIdx.x;
    const int wrp  = tid >> 5;
    const int lane = tid & 31;

    __shared__ float w[ROWS_PB][WPAD];
    __shared__ float cs_c[N_STAGES][64], cs_s[N_STAGES][64];
    __shared__ int   pi[N_STAGES][64], pj[N_STAGES][64];
    __shared__ float csc[GROUP];
    __shared__ float qs[ROWS_PB], qz[ROWS_PB];

    // ---- fused x -> fp16 conversion (independent stream) ----
    {
        const int blk = blockIdx.y * NGROUPS + blockIdx.x;
        const float* xs = x + (size_t)blk * XCHUNK;
        __half* xd = g_x_h + (size_t)blk * XCHUNK;
        #pragma unroll
        for (int t = 0; t < (int)(XCHUNK / (256 * 8)); t++) {
            size_t i = ((size_t)(t * 256 + tid)) * 8;
            float4 v0 = *reinterpret_cast<const float4*>(xs + i);
            float4 v1 = *reinterpret_cast<const float4*>(xs + i + 4);
            __half2 h[4];
            h[0] = __floats2half2_rn(v0.x, v0.y);
            h[1] = __floats2half2_rn(v0.z, v0.w);
            h[2] = __floats2half2_rn(v1.x, v1.y);
            h[3] = __floats2half2_rn(v1.z, v1.w);
            *reinterpret_cast<uint4*>(xd + i) =
                *reinterpret_cast<const uint4*>(h);
        }
    }

    // ---- block-wide tables ----
    if (tid < GROUP) csc[tid] = channel_scales[g * GROUP + tid];
    {
        int st = tid >> 6, p = tid & 63;
        float s, c;
        sincosf(theta[st * (IN_F / 2) + g * 64 + p], &s, &c);
        cs_c[st][p] = c;
        cs_s[st][p] = s;
        pi[st][p] = pairs[st * IN_F + g * GROUP + 2 * p];
        pj[st][p] = pairs[st * IN_F + g * GROUP + 2 * p + 1];
    }
    __syncthreads();

    // ---- per-warp: 8 rows, warp-synchronous ----
    const int rbase = wrp * 8;

    if (lane < 8) {
        int gi = (row0 + rbase + lane) * NGROUPS + g;
        qs[rbase + lane] = fminf(fmaxf(q_scale[gi], 1e-5f), 1e5f);
        qz[rbase + lane] = fminf(fmaxf(-rintf(q_zp[gi]), 0.0f), QMAXF);
    }

    const int c4 = lane * 4;
    #pragma unroll
    for (int rr = 0; rr < 8; rr++) {
        float4 v = *reinterpret_cast<const float4*>(
            weight + (size_t)(row0 + rbase + rr) * IN_F + g * GROUP + c4);
        v.x *= csc[c4];
        v.y *= csc[c4 + 1];
        v.z *= csc[c4 + 2];
        v.w *= csc[c4 + 3];
        *reinterpret_cast<float4*>(&w[rbase + rr][c4]) = v;
    }
    __syncwarp();

    #pragma unroll
    for (int st = 0; st < N_STAGES; st++) {
        #pragma unroll
        for (int t = 0; t < 16; t++) {
            int v = lane + t * 32;
            int r = rbase + (v >> 6);
            int p = v & 63;
            float c = cs_c[st][p], s = cs_s[st][p];
            int i = pi[st][p], j = pj[st][p];
            float xi = w[r][i], xj = w[r][j];
            w[r][i] =  xi * c + xj * s;
            w[r][j] = -xi * s + xj * c;
        }
        __syncwarp();
    }

    #pragma unroll
    for (int t = 0; t < 32; t++) {
        int v = lane + t * 32;
        int r = rbase + (v >> 7);
        int c = v & 127;
        float s = qs[r], rzp = qz[r];
        float q = rintf(w[r][c] / s) + rzp;
        q = fminf(fmaxf(q, 0.0f), QMAXF);
        w[r][c] = (q - rzp) * s;
    }
    __syncwarp();

    #pragma unroll
    for (int st = N_STAGES - 1; st >= 0; st--) {
        #pragma unroll
        for (int t = 0; t < 16; t++) {
            int v = lane + t * 32;
            int r = rbase + (v >> 6);
            int p = v & 63;
            float c = cs_c[st][p], s = cs_s[st][p];
            int i = pi[st][p], j = pj[st][p];
            float xi = w[r][i], xj = w[r][j];
            w[r][i] = xi * c - xj * s;
            w[r][j] = xi * s + xj * c;
        }
        __syncwarp();
    }

    #pragma unroll
    for (int rr = 0; rr < 8; rr++) {
        __half2 h[2];
        h[0] = __floats2half2_rn(w[rbase + rr][c4]     / csc[c4],
                                 w[rbase + rr][c4 + 1] / csc[c4 + 1]);
        h[1] = __floats2half2_rn(w[rbase + rr][c4 + 2] / csc[c4 + 2],
                                 w[rbase + rr][c4 + 3] / csc[c4 + 3]);
        *reinterpret_cast<uint2*>(
            g_w_h + (size_t)(row0 + rbase + rr) * IN_F + g * GROUP + c4) =
            *reinterpret_cast<const uint2*>(h);
    }
}

// ---------------------------------------------------------------------------
// Kernel 2: fp16 mma.sync GEMM. CTA 128x128, 256 threads, warp tile 64x32,
// BK=64, 3-stage cp.async, 96KB smem -> 2 CTAs/SM (cross-CTA bubble overlap).
// ---------------------------------------------------------------------------
#define BM 128
#define BN 128
#define BK 64
#define KSTAGES 3
#define NTHREADS 256
#define A_STAGE_BYTES (BM * BK * 2)                       // 16384
#define B_STAGE_BYTES (BN * BK * 2)                       // 16384
#define STAGE_BYTES   (A_STAGE_BYTES + B_STAGE_BYTES)     // 32768
#define GEMM_SMEM     (KSTAGES * STAGE_BYTES)             // 98304
#define NKT           (IN_F / BK)                         // 64

__device__ __forceinline__ uint32_t smem_u32(const void* p) {
    uint32_t a;
    asm("{ .reg .u64 t; cvta.to.shared.u64 t, %1; cvt.u32.u64 %0, t; }"
        : "=r"(a) : "l"(p));
    return a;
}
__device__ __forceinline__ void cp_async16(uint32_t saddr, const void* gptr) {
    asm volatile("cp.async.cg.shared.global [%0], [%1], 16;"
                 :: "r"(saddr), "l"(gptr));
}
#define CP_COMMIT() asm volatile("cp.async.commit_group;" ::: "memory")
#define CP_WAIT(n)  asm volatile("cp.async.wait_group %0;" :: "n"(n) : "memory")

__device__ __forceinline__ void ldmatrix_x4(uint32_t* r, uint32_t addr) {
    asm volatile("ldmatrix.sync.aligned.m8n8.x4.shared.b16 {%0,%1,%2,%3}, [%4];"
                 : "=r"(r[0]), "=r"(r[1]), "=r"(r[2]), "=r"(r[3]) : "r"(addr));
}
__device__ __forceinline__ void mma16816(float* c, const uint32_t* a,
                                         const uint32_t* b) {
    asm volatile("mma.sync.aligned.m16n8k16.row.col.f32.f16.f16.f32 "
                 "{%0,%1,%2,%3}, {%4,%5,%6,%7}, {%8,%9}, {%0,%1,%2,%3};"
                 : "+f"(c[0]), "+f"(c[1]), "+f"(c[2]), "+f"(c[3])
                 : "r"(a[0]), "r"(a[1]), "r"(a[2]), "r"(a[3]),
                   "r"(b[0]), "r"(b[1]));
}

__global__ __launch_bounds__(NTHREADS, 2) void gemm_mma_kernel(
    const float* __restrict__ bias, float* __restrict__ C)
{
    extern __shared__ char smem[];
    const uint32_t sbase = smem_u32(smem);
    const int tid  = threadIdx.x;
    const int wid  = tid >> 5;
    const int lane = tid & 31;
    const int bn = blockIdx.x;
    const int bm = blockIdx.y;
    const int warp_m = wid >> 2;         // 0..1 -> 64 rows
    const int warp_n = wid & 3;          // 0..3 -> 32 cols

    const __half* Ag0 = g_x_h + (size_t)(bm * BM) * IN_F;
    const __half* Bg0 = g_w_h + (size_t)(bn * BN) * IN_F;

    float acc[4][4][4];
    #pragma unroll
    for (int i = 0; i < 4; i++)
        #pragma unroll
        for (int j = 0; j < 4; j++)
            #pragma unroll
            for (int k = 0; k < 4; k++) acc[i][j][k] = 0.0f;

    auto load_stage = [&](int kt) {
        const int buf = (kt % KSTAGES);
        const int ko  = kt * BK;
        const __half* Ag = Ag0 + ko;
        const __half* Bg = Bg0 + ko;
        const uint32_t sA = sbase + buf * STAGE_BYTES;
        const uint32_t sB = sA + A_STAGE_BYTES;
        #pragma unroll
        for (int t = 0; t < 4; t++) {        // A: 1024 chunks / 256 thr
            int v = tid + t * NTHREADS;
            int r = v >> 3, c = v & 7;
            uint32_t off = (uint32_t)(r << 7) + (uint32_t)((c ^ (r & 7)) << 4);
            cp_async16(sA + off, Ag + (size_t)r * IN_F + c * 8);
        }
        #pragma unroll
        for (int t = 0; t < 4; t++) {        // B: 1024 chunks / 256 thr
            int v = tid + t * NTHREADS;
            int r = v >> 3, c = v & 7;
            uint32_t off = (uint32_t)(r << 7) + (uint32_t)((c ^ (r & 7)) << 4);
            cp_async16(sB + off, Bg + (size_t)r * IN_F + c * 8);
        }
    };

    const int m_lane  = warp_m * 64 + (lane & 15);
    const int a_half  = lane >> 4;
    const int xa      = m_lane & 7;
    const int n_lane  = warp_n * 32 + (lane & 7) + ((lane >> 4) << 3);
    const int b_half  = (lane >> 3) & 1;
    const int xb      = n_lane & 7;

    load_stage(0);
    CP_COMMIT();
    load_stage(1);
    CP_COMMIT();

    for (int kt = 0; kt < NKT; kt++) {
        CP_WAIT(1);
        __syncthreads();

        if (kt + 2 < NKT) load_stage(kt + 2);
        CP_COMMIT();

        const int buf = kt % KSTAGES;
        const uint32_t sA = sbase + buf * STAGE_BYTES;
        const uint32_t sB = sA + A_STAGE_BYTES;
        const uint32_t aRow = sA + (uint32_t)(m_lane << 7);
        const uint32_t bRow = sB + (uint32_t)(n_lane << 7);

        #pragma unroll
        for (int kk = 0; kk < 4; kk++) {
            uint32_t a_frag[4][4];
            uint32_t b_frag[2][4];
            const uint32_t ac = (uint32_t)(((kk * 2 + a_half) ^ xa) << 4);
            const uint32_t bc = (uint32_t)(((kk * 2 + b_half) ^ xb) << 4);
            #pragma unroll
            for (int mt = 0; mt < 4; mt++)
                ldmatrix_x4(a_frag[mt], aRow + (uint32_t)(mt << 11) + ac);
            #pragma unroll
            for (int nt = 0; nt < 2; nt++)
                ldmatrix_x4(b_frag[nt], bRow + (uint32_t)(nt << 11) + bc);
            #pragma unroll
            for (int mt = 0; mt < 4; mt++) {
                #pragma unroll
                for (int nt = 0; nt < 2; nt++) {
                    mma16816(acc[mt][2 * nt],     a_frag[mt], &b_frag[nt][0]);
                    mma16816(acc[mt][2 * nt + 1], a_frag[mt], &b_frag[nt][2]);
                }
            }
        }
    }

    const int row_base = bm * BM + warp_m * 64 + (lane >> 2);
    const int col_base = bn * BN + warp_n * 32 + 2 * (lane & 3);
    #pragma unroll
    for (int mt = 0; mt < 4; mt++) {
        const int r0 = row_base + mt * 16;
        #pragma unroll
        for (int n8 = 0; n8 < 4; n8++) {
            const int col = col_base + n8 * 8;
            float2 bv = *reinterpret_cast<const float2*>(bias + col);
            float2 o0, o1;
            o0.x = acc[mt][n8][0] + bv.x;
            o0.y = acc[mt][n8][1] + bv.y;
            o1.x = acc[mt][n8][2] + bv.x;
            o1.y = acc[mt][n8][3] + bv.y;
            *reinterpret_cast<float2*>(C + (size_t)r0 * OUT_F + col)       = o0;
            *reinterpret_cast<float2*>(C + (size_t)(r0 + 8) * OUT_F + col) = o1;
        }
    }
}

// ---------------------------------------------------------------------------
// Launch
// ---------------------------------------------------------------------------
extern "C" void kernel_launch(void* const* d_in, const int* in_sizes, int n_in,
                              void* d_out, int out_size)
{
    const float* x              = (const float*)d_in[0];
    const float* weight         = (const float*)d_in[1];
    const float* bias           = (const float*)d_in[2];
    const float* channel_scales = (const float*)d_in[3];
    const float* theta          = (const float*)d_in[4];
    const float* q_scale        = (const float*)d_in[5];
    const float* q_zp           = (const float*)d_in[6];
    const int*   pairs          = (const int*)d_in[7];
    float* out = (float*)d_out;

    cudaFuncSetAttribute(gemm_mma_kernel,
                         cudaFuncAttributeMaxDynamicSharedMemorySize, GEMM_SMEM);

    dim3 tgrid(NGROUPS, OUT_F / ROWS_PB);
    transform_kernel<<<tgrid, 256>>>(weight, channel_scales, theta,
                                     q_scale, q_zp, pairs, x);

    dim3 grid(OUT_F / BN, N_TOK / BM);
    gemm_mma_kernel<<<grid, NTHREADS, GEMM_SMEM>>>(bias, out);
}

// round 12
// speedup vs baseline: 1.0276x; 1.0276x over previous
#include <cuda_runtime.h>
#include <cuda_fp16.h>
#include <cstdint>

#define IN_F     4096
#define OUT_F    4096
#define N_TOK    8192
#define GROUP    128
#define NGROUPS  (IN_F / GROUP)
#define N_STAGES 4
#define QMAXF    15.0f

// ---------------- scratch (device globals; no runtime allocation) ----------
__device__ __half g_w_h[(size_t)OUT_F * IN_F];
__device__ __half g_x_h[(size_t)N_TOK * IN_F];

// ---------------------------------------------------------------------------
// Kernel 1: fused weight transform + x->fp16 conversion (R10, best measured).
// ---------------------------------------------------------------------------
#define ROWS_PB 64
#define WPAD    132
#define TBLOCKS (NGROUPS * (OUT_F / ROWS_PB))          // 2048
#define XCHUNK  ((size_t)N_TOK * IN_F / TBLOCKS)       // 16384 elems / block

__global__ __launch_bounds__(256) void transform_kernel(
    const float* __restrict__ weight,
    const float* __restrict__ channel_scales,
    const float* __restrict__ theta,
    const float* __restrict__ q_scale,
    const float* __restrict__ q_zp,
    const int*   __restrict__ pairs,
    const float* __restrict__ x)
{
    const int g    = blockIdx.x;
    const int row0 = blockIdx.y * ROWS_PB;
    const int tid  = threadIdx.x;
    const int wrp  = tid >> 5;
    const int lane = tid & 31;

    __shared__ float w[ROWS_PB][WPAD];
    __shared__ float cs_c[N_STAGES][64], cs_s[N_STAGES][64];
    __shared__ int   pi[N_STAGES][64], pj[N_STAGES][64];
    __shared__ float csc[GROUP];
    __shared__ float qs[ROWS_PB], qz[ROWS_PB];

    // ---- fused x -> fp16 conversion (independent stream) ----
    {
        const int blk = blockIdx.y * NGROUPS + blockIdx.x;
        const float* xs = x + (size_t)blk * XCHUNK;
        __half* xd = g_x_h + (size_t)blk * XCHUNK;
        #pragma unroll
        for (int t = 0; t < (int)(XCHUNK / (256 * 8)); t++) {
            size_t i = ((size_t)(t * 256 + tid)) * 8;
            float4 v0 = *reinterpret_cast<const float4*>(xs + i);
            float4 v1 = *reinterpret_cast<const float4*>(xs + i + 4);
            __half2 h[4];
            h[0] = __floats2half2_rn(v0.x, v0.y);
            h[1] = __floats2half2_rn(v0.z, v0.w);
            h[2] = __floats2half2_rn(v1.x, v1.y);
            h[3] = __floats2half2_rn(v1.z, v1.w);
            *reinterpret_cast<uint4*>(xd + i) =
                *reinterpret_cast<const uint4*>(h);
        }
    }

    // ---- block-wide tables ----
    if (tid < GROUP) csc[tid] = channel_scales[g * GROUP + tid];
    {
        int st = tid >> 6, p = tid & 63;
        float s, c;
        sincosf(theta[st * (IN_F / 2) + g * 64 + p], &s, &c);
        cs_c[st][p] = c;
        cs_s[st][p] = s;
        pi[st][p] = pairs[st * IN_F + g * GROUP + 2 * p];
        pj[st][p] = pairs[st * IN_F + g * GROUP + 2 * p + 1];
    }
    __syncthreads();

    // ---- per-warp: 8 rows, warp-synchronous ----
    const int rbase = wrp * 8;

    if (lane < 8) {
        int gi = (row0 + rbase + lane) * NGROUPS + g;
        qs[rbase + lane] = fminf(fmaxf(q_scale[gi], 1e-5f), 1e5f);
        qz[rbase + lane] = fminf(fmaxf(-rintf(q_zp[gi]), 0.0f), QMAXF);
    }

    const int c4 = lane * 4;
    #pragma unroll
    for (int rr = 0; rr < 8; rr++) {
        float4 v = *reinterpret_cast<const float4*>(
            weight + (size_t)(row0 + rbase + rr) * IN_F + g * GROUP + c4);
        v.x *= csc[c4];
        v.y *= csc[c4 + 1];
        v.z *= csc[c4 + 2];
        v.w *= csc[c4 + 3];
        *reinterpret_cast<float4*>(&w[rbase + rr][c4]) = v;
    }
    __syncwarp();

    #pragma unroll
    for (int st = 0; st < N_STAGES; st++) {
        #pragma unroll
        for (int t = 0; t < 16; t++) {
            int v = lane + t * 32;
            int r = rbase + (v >> 6);
            int p = v & 63;
            float c = cs_c[st][p], s = cs_s[st][p];
            int i = pi[st][p], j = pj[st][p];
            float xi = w[r][i], xj = w[r][j];
            w[r][i] =  xi * c + xj * s;
            w[r][j] = -xi * s + xj * c;
        }
        __syncwarp();
    }

    #pragma unroll
    for (int t = 0; t < 32; t++) {
        int v = lane + t * 32;
        int r = rbase + (v >> 7);
        int c = v & 127;
        float s = qs[r], rzp = qz[r];
        float q = rintf(w[r][c] / s) + rzp;
        q = fminf(fmaxf(q, 0.0f), QMAXF);
        w[r][c] = (q - rzp) * s;
    }
    __syncwarp();

    #pragma unroll
    for (int st = N_STAGES - 1; st >= 0; st--) {
        #pragma unroll
        for (int t = 0; t < 16; t++) {
            int v = lane + t * 32;
            int r = rbase + (v >> 6);
            int p = v & 63;
            float c = cs_c[st][p], s = cs_s[st][p];
            int i = pi[st][p], j = pj[st][p];
            float xi = w[r][i], xj = w[r][j];
            w[r][i] = xi * c - xj * s;
            w[r][j] = xi * s + xj * c;
        }
        __syncwarp();
    }

    #pragma unroll
    for (int rr = 0; rr < 8; rr++) {
        __half2 h[2];
        h[0] = __floats2half2_rn(w[rbase + rr][c4]     / csc[c4],
                                 w[rbase + rr][c4 + 1] / csc[c4 + 1]);
        h[1] = __floats2half2_rn(w[rbase + rr][c4 + 2] / csc[c4 + 2],
                                 w[rbase + rr][c4 + 3] / csc[c4 + 3]);
        *reinterpret_cast<uint2*>(
            g_w_h + (size_t)(row0 + rbase + rr) * IN_F + g * GROUP + c4) =
            *reinterpret_cast<const uint2*>(h);
    }
}

// ---------------------------------------------------------------------------
// Kernel 2: PERSISTENT fp16 mma.sync GEMM. CTA 128x256, 512 threads,
// warp tile 64x32, BK=128, 2-stage (192KB). grid=148; each CTA loops over
// ~7 tiles with the cp.async depth-1 prefetch flattened across tile
// boundaries (no per-wave pipeline drain).
// ---------------------------------------------------------------------------
#define BM 128
#define BN 256
#define BK 128
#define NTHREADS 512
#define GRID_P   148
#define NTILES   ((OUT_F / BN) * (N_TOK / BM))            // 16*64 = 1024
#define ITERS_PT (IN_F / BK)                              // 32
#define A_STAGE_BYTES (BM * BK * 2)                       // 32768
#define B_STAGE_BYTES (BN * BK * 2)                       // 65536
#define STAGE_BYTES   (A_STAGE_BYTES + B_STAGE_BYTES)     // 98304
#define GEMM_SMEM     (2 * STAGE_BYTES)                   // 196608

__device__ __forceinline__ uint32_t smem_u32(const void* p) {
    uint32_t a;
    asm("{ .reg .u64 t; cvta.to.shared.u64 t, %1; cvt.u32.u64 %0, t; }"
        : "=r"(a) : "l"(p));
    return a;
}
__device__ __forceinline__ void cp_async16(uint32_t saddr, const void* gptr) {
    asm volatile("cp.async.cg.shared.global [%0], [%1], 16;"
                 :: "r"(saddr), "l"(gptr));
}
#define CP_COMMIT() asm volatile("cp.async.commit_group;" ::: "memory")
#define CP_WAIT(n)  asm volatile("cp.async.wait_group %0;" :: "n"(n) : "memory")

__device__ __forceinline__ void ldmatrix_x4(uint32_t* r, uint32_t addr) {
    asm volatile("ldmatrix.sync.aligned.m8n8.x4.shared.b16 {%0,%1,%2,%3}, [%4];"
                 : "=r"(r[0]), "=r"(r[1]), "=r"(r[2]), "=r"(r[3]) : "r"(addr));
}
__device__ __forceinline__ void mma16816(float* c, const uint32_t* a,
                                         const uint32_t* b) {
    asm volatile("mma.sync.aligned.m16n8k16.row.col.f32.f16.f16.f32 "
                 "{%0,%1,%2,%3}, {%4,%5,%6,%7}, {%8,%9}, {%0,%1,%2,%3};"
                 : "+f"(c[0]), "+f"(c[1]), "+f"(c[2]), "+f"(c[3])
                 : "r"(a[0]), "r"(a[1]), "r"(a[2]), "r"(a[3]),
                   "r"(b[0]), "r"(b[1]));
}

__global__ __launch_bounds__(NTHREADS, 1) void gemm_mma_kernel(
    const float* __restrict__ bias, float* __restrict__ C)
{
    extern __shared__ char smem[];
    const uint32_t sbase = smem_u32(smem);
    const int tid  = threadIdx.x;
    const int wid  = tid >> 5;
    const int lane = tid & 31;
    const int cta  = blockIdx.x;
    const int warp_m = wid >> 3;
    const int warp_n = wid & 7;

    const int my_tiles = (NTILES - cta + GRID_P - 1) / GRID_P;
    const int total_it = my_tiles * ITERS_PT;

    // load a stage for flattened iteration `it` (tile-crossing prefetch)
    auto load_stage = [&](int it) {
        const int tile = cta + (it >> 5) * GRID_P;
        const int bn   = tile & 15;
        const int bm   = tile >> 4;
        const int ko   = (it & 31) * BK;
        const __half* Ag = g_x_h + (size_t)(bm * BM) * IN_F + ko;
        const __half* Bg = g_w_h + (size_t)(bn * BN) * IN_F + ko;
        const uint32_t sA = sbase + (it & 1) * STAGE_BYTES;
        const uint32_t sB = sA + A_STAGE_BYTES;
        #pragma unroll
        for (int t = 0; t < 4; t++) {        // A: 2048 chunks / 512 thr
            int v = tid + t * NTHREADS;
            int r = v >> 4, c = v & 15;
            uint32_t off = (uint32_t)(r << 8) + (uint32_t)((c ^ (r & 7)) << 4);
            cp_async16(sA + off, Ag + (size_t)r * IN_F + c * 8);
        }
        #pragma unroll
        for (int t = 0; t < 8; t++) {        // B: 4096 chunks / 512 thr
            int v = tid + t * NTHREADS;
            int r = v >> 4, c = v & 15;
            uint32_t off = (uint32_t)(r << 8) + (uint32_t)((c ^ (r & 7)) << 4);
            cp_async16(sB + off, Bg + (size_t)r * IN_F + c * 8);
        }
    };

    const int m_lane  = warp_m * 64 + (lane & 15);
    const int a_half  = lane >> 4;
    const int xa      = m_lane & 7;
    const int n_lane  = warp_n * 32 + (lane & 7) + ((lane >> 4) << 3);
    const int b_half  = (lane >> 3) & 1;
    const int xb      = n_lane & 7;

    float acc[4][4][4];
    #pragma unroll
    for (int i = 0; i < 4; i++)
        #pragma unroll
        for (int j = 0; j < 4; j++)
            #pragma unroll
            for (int k = 0; k < 4; k++) acc[i][j][k] = 0.0f;

    if (total_it == 0) return;
    load_stage(0);
    CP_COMMIT();

    for (int it = 0; it < total_it; it++) {
        CP_WAIT(0);
        __syncthreads();

        if (it + 1 < total_it) load_stage(it + 1);
        CP_COMMIT();

        const uint32_t sA = sbase + (it & 1) * STAGE_BYTES;
        const uint32_t sB = sA + A_STAGE_BYTES;
        const uint32_t aRow = sA + (uint32_t)(m_lane << 8);
        const uint32_t bRow = sB + (uint32_t)(n_lane << 8);

        #pragma unroll
        for (int kk = 0; kk < 8; kk++) {
            uint32_t a_frag[4][4];
            uint32_t b_frag[2][4];
            const uint32_t ac = (uint32_t)(((kk * 2 + a_half) ^ xa) << 4);
            const uint32_t bc = (uint32_t)(((kk * 2 + b_half) ^ xb) << 4);
            #pragma unroll
            for (int mt = 0; mt < 4; mt++)
                ldmatrix_x4(a_frag[mt], aRow + (uint32_t)(mt << 12) + ac);
            #pragma unroll
            for (int nt = 0; nt < 2; nt++)
                ldmatrix_x4(b_frag[nt], bRow + (uint32_t)(nt << 12) + bc);
            #pragma unroll
            for (int mt = 0; mt < 4; mt++) {
                #pragma unroll
                for (int nt = 0; nt < 2; nt++) {
                    mma16816(acc[mt][2 * nt],     a_frag[mt], &b_frag[nt][0]);
                    mma16816(acc[mt][2 * nt + 1], a_frag[mt], &b_frag[nt][2]);
                }
            }
        }

        // epilogue at end of each tile; overlaps next tile's prefetch
        if ((it & 31) == 31) {
            const int tile = cta + (it >> 5) * GRID_P;
            const int bn   = tile & 15;
            const int bm   = tile >> 4;
            const int row_base = bm * BM + warp_m * 64 + (lane >> 2);
            const int col_base = bn * BN + warp_n * 32 + 2 * (lane & 3);
            #pragma unroll
            for (int mt = 0; mt < 4; mt++) {
                const int r0 = row_base + mt * 16;
                #pragma unroll
                for (int n8 = 0; n8 < 4; n8++) {
                    const int col = col_base + n8 * 8;
                    float2 bv = *reinterpret_cast<const float2*>(bias + col);
                    float2 o0, o1;
                    o0.x = acc[mt][n8][0] + bv.x;
                    o0.y = acc[mt][n8][1] + bv.y;
                    o1.x = acc[mt][n8][2] + bv.x;
                    o1.y = acc[mt][n8][3] + bv.y;
                    *reinterpret_cast<float2*>(
                        C + (size_t)r0 * OUT_F + col) = o0;
                    *reinterpret_cast<float2*>(
                        C + (size_t)(r0 + 8) * OUT_F + col) = o1;
                    #pragma unroll
                    for (int k = 0; k < 4; k++) acc[mt][n8][k] = 0.0f;
                }
            }
        }
    }
}

// ---------------------------------------------------------------------------
// Launch
// ---------------------------------------------------------------------------
extern "C" void kernel_launch(void* const* d_in, const int* in_sizes, int n_in,
                              void* d_out, int out_size)
{
    const float* x              = (const float*)d_in[0];
    const float* weight         = (const float*)d_in[1];
    const float* bias           = (const float*)d_in[2];
    const float* channel_scales = (const float*)d_in[3];
    const float* theta          = (const float*)d_in[4];
    const float* q_scale        = (const float*)d_in[5];
    const float* q_zp           = (const float*)d_in[6];
    const int*   pairs          = (const int*)d_in[7];
    float* out = (float*)d_out;

    cudaFuncSetAttribute(gemm_mma_kernel,
                         cudaFuncAttributeMaxDynamicSharedMemorySize, GEMM_SMEM);

    dim3 tgrid(NGROUPS, OUT_F / ROWS_PB);
    transform_kernel<<<tgrid, 256>>>(weight, channel_scales, theta,
                                     q_scale, q_zp, pairs, x);

    gemm_mma_kernel<<<GRID_P, NTHREADS, GEMM_SMEM>>>(bias, out);
}

// round 13
// speedup vs baseline: 1.0729x; 1.0440x over previous
#include <cuda_runtime.h>
#include <cuda_fp16.h>
#include <cstdint>

#define IN_F     4096
#define OUT_F    4096
#define N_TOK    8192
#define GROUP    128
#define NGROUPS  (IN_F / GROUP)
#define N_STAGES 4
#define QMAXF    15.0f

// ---------------- scratch (device globals; no runtime allocation) ----------
__device__ __half g_w_h[(size_t)OUT_F * IN_F];
__device__ __half g_x_h[(size_t)N_TOK * IN_F];

// ---------------------------------------------------------------------------
// Kernel 1: fused weight transform + x->fp16 conversion.
// TRANSPOSED smem tile wT[channel][row] with odd padding: every rotation LDS
// is stride-1 across lanes (rows) -> zero bank conflicts. Block = (group g,
// 32 rows), 21.8KB smem, 8 blocks/SM.
// ---------------------------------------------------------------------------
#define ROWS_PB 32
#define RPAD    33
#define TBLOCKS (NGROUPS * (OUT_F / ROWS_PB))          // 4096
#define XCHUNK  ((size_t)N_TOK * IN_F / TBLOCKS)       // 8192 elems / block

__global__ __launch_bounds__(256) void transform_kernel(
    const float* __restrict__ weight,
    const float* __restrict__ channel_scales,
    const float* __restrict__ theta,
    const float* __restrict__ q_scale,
    const float* __restrict__ q_zp,
    const int*   __restrict__ pairs,
    const float* __restrict__ x)
{
    const int g    = blockIdx.x;              // 0..31
    const int row0 = blockIdx.y * ROWS_PB;    // 0..4064
    const int tid  = threadIdx.x;
    const int wrp  = tid >> 5;                // 0..7
    const int lane = tid & 31;

    __shared__ float wT[GROUP][RPAD];         // [channel][row] 128x33
    __shared__ float cs_c[N_STAGES][64], cs_s[N_STAGES][64];
    __shared__ int   pi[N_STAGES][64], pj[N_STAGES][64];
    __shared__ float csc[GROUP];
    __shared__ float qs[ROWS_PB], qz[ROWS_PB];

    // ---- fused x -> fp16 conversion (independent DRAM stream) ----
    {
        const int blk = blockIdx.y * NGROUPS + blockIdx.x;   // 0..4095
        const float* xs = x + (size_t)blk * XCHUNK;
        __half* xd = g_x_h + (size_t)blk * XCHUNK;
        #pragma unroll
        for (int t = 0; t < (int)(XCHUNK / (256 * 8)); t++) {  // 4 iters
            size_t i = ((size_t)(t * 256 + tid)) * 8;
            float4 v0 = *reinterpret_cast<const float4*>(xs + i);
            float4 v1 = *reinterpret_cast<const float4*>(xs + i + 4);
            __half2 h[4];
            h[0] = __floats2half2_rn(v0.x, v0.y);
            h[1] = __floats2half2_rn(v0.z, v0.w);
            h[2] = __floats2half2_rn(v1.x, v1.y);
            h[3] = __floats2half2_rn(v1.z, v1.w);
            *reinterpret_cast<uint4*>(xd + i) =
                *reinterpret_cast<const uint4*>(h);
        }
    }

    // ---- tables ----
    if (tid < GROUP) csc[tid] = channel_scales[g * GROUP + tid];
    {
        int st = tid >> 6, p = tid & 63;      // 256 = 4 stages x 64 pairs
        float s, c;
        sincosf(theta[st * (IN_F / 2) + g * 64 + p], &s, &c);
        cs_c[st][p] = c;
        cs_s[st][p] = s;
        pi[st][p] = pairs[st * IN_F + g * GROUP + 2 * p];
        pj[st][p] = pairs[st * IN_F + g * GROUP + 2 * p + 1];
    }
    if (tid < ROWS_PB) {
        int gi = (row0 + tid) * NGROUPS + g;
        qs[tid] = fminf(fmaxf(q_scale[gi], 1e-5f), 1e5f);
        qz[tid] = fminf(fmaxf(-rintf(q_zp[gi]), 0.0f), QMAXF);
    }
    __syncthreads();

    // ---- transposed load + channel scale ----
    // warp wrp owns local rows wrp*4 .. wrp*4+3; lane -> (row, col-chunk)
    const int lr = wrp * 4 + (lane >> 3);     // local row 0..31
    #pragma unroll
    for (int it = 0; it < 4; it++) {
        int c4 = ((lane & 7) + it * 8) * 4;   // 0,32,64,96 + lane part
        float4 v = *reinterpret_cast<const float4*>(
            weight + (size_t)(row0 + lr) * IN_F + g * GROUP + c4);
        v.x *= csc[c4];
        v.y *= csc[c4 + 1];
        v.z *= csc[c4 + 2];
        v.w *= csc[c4 + 3];
        wT[c4 + 0][lr] = v.x;                 // banks (4a+e+4w+b): all distinct
        wT[c4 + 1][lr] = v.y;
        wT[c4 + 2][lr] = v.z;
        wT[c4 + 3][lr] = v.w;
    }
    __syncthreads();

    // ---- forward rotations: lane = row, warp instruction = one pair ----
    #pragma unroll
    for (int st = 0; st < N_STAGES; st++) {
        #pragma unroll
        for (int t = 0; t < 8; t++) {
            int p = wrp + t * 8;
            float c = cs_c[st][p], s = cs_s[st][p];
            int i = pi[st][p], j = pj[st][p];
            float xi = wT[i][lane], xj = wT[j][lane];   // stride-1: no conflicts
            wT[i][lane] =  xi * c + xj * s;
            wT[j][lane] = -xi * s + xj * c;
        }
        __syncthreads();
    }

    // ---- quant-dequant: lane = row -> per-thread scalars, conflict-free ----
    {
        float s = qs[lane], rzp = qz[lane];
        #pragma unroll
        for (int t = 0; t < 16; t++) {
            int c = wrp + t * 8;
            float q = rintf(wT[c][lane] / s) + rzp;
            q = fminf(fmaxf(q, 0.0f), QMAXF);
            wT[c][lane] = (q - rzp) * s;
        }
    }
    __syncthreads();

    // ---- inverse rotations ----
    #pragma unroll
    for (int st = N_STAGES - 1; st >= 0; st--) {
        #pragma unroll
        for (int t = 0; t < 8; t++) {
            int p = wrp + t * 8;
            float c = cs_c[st][p], s = cs_s[st][p];
            int i = pi[st][p], j = pj[st][p];
            float xi = wT[i][lane], xj = wT[j][lane];
            wT[i][lane] = xi * c - xj * s;
            wT[j][lane] = xi * s + xj * c;
        }
        __syncthreads();
    }

    // ---- unscale + fp16 store ----
    #pragma unroll
    for (int it = 0; it < 8; it++) {
        int c = (((lane & 7) + it * 8)) * 2;  // even channel
        float a = wT[c][lr]     / csc[c];
        float b = wT[c + 1][lr] / csc[c + 1];
        *reinterpret_cast<__half2*>(
            g_w_h + (size_t)(row0 + lr) * IN_F + g * GROUP + c) =
            __floats2half2_rn(a, b);
    }
}

// ---------------------------------------------------------------------------
// Kernel 2: PERSISTENT fp16 mma.sync GEMM (R12, measured 612us — parked).
// ---------------------------------------------------------------------------
#define BM 128
#define BN 256
#define BK 128
#define NTHREADS 512
#define GRID_P   148
#define NTILES   ((OUT_F / BN) * (N_TOK / BM))            // 1024
#define ITERS_PT (IN_F / BK)                              // 32
#define A_STAGE_BYTES (BM * BK * 2)                       // 32768
#define B_STAGE_BYTES (BN * BK * 2)                       // 65536
#define STAGE_BYTES   (A_STAGE_BYTES + B_STAGE_BYTES)     // 98304
#define GEMM_SMEM     (2 * STAGE_BYTES)                   // 196608

__device__ __forceinline__ uint32_t smem_u32(const void* p) {
    uint32_t a;
    asm("{ .reg .u64 t; cvta.to.shared.u64 t, %1; cvt.u32.u64 %0, t; }"
        : "=r"(a) : "l"(p));
    return a;
}
__device__ __forceinline__ void cp_async16(uint32_t saddr, const void* gptr) {
    asm volatile("cp.async.cg.shared.global [%0], [%1], 16;"
                 :: "r"(saddr), "l"(gptr));
}
#define CP_COMMIT() asm volatile("cp.async.commit_group;" ::: "memory")
#define CP_WAIT(n)  asm volatile("cp.async.wait_group %0;" :: "n"(n) : "memory")

__device__ __forceinline__ void ldmatrix_x4(uint32_t* r, uint32_t addr) {
    asm volatile("ldmatrix.sync.aligned.m8n8.x4.shared.b16 {%0,%1,%2,%3}, [%4];"
                 : "=r"(r[0]), "=r"(r[1]), "=r"(r[2]), "=r"(r[3]) : "r"(addr));
}
__device__ __forceinline__ void mma16816(float* c, const uint32_t* a,
                                         const uint32_t* b) {
    asm volatile("mma.sync.aligned.m16n8k16.row.col.f32.f16.f16.f32 "
                 "{%0,%1,%2,%3}, {%4,%5,%6,%7}, {%8,%9}, {%0,%1,%2,%3};"
                 : "+f"(c[0]), "+f"(c[1]), "+f"(c[2]), "+f"(c[3])
                 : "r"(a[0]), "r"(a[1]), "r"(a[2]), "r"(a[3]),
                   "r"(b[0]), "r"(b[1]));
}

__global__ __launch_bounds__(NTHREADS, 1) void gemm_mma_kernel(
    const float* __restrict__ bias, float* __restrict__ C)
{
    extern __shared__ char smem[];
    const uint32_t sbase = smem_u32(smem);
    const int tid  = threadIdx.x;
    const int wid  = tid >> 5;
    const int lane = tid & 31;
    const int cta  = blockIdx.x;
    const int warp_m = wid >> 3;
    const int warp_n = wid & 7;

    const int my_tiles = (NTILES - cta + GRID_P - 1) / GRID_P;
    const int total_it = my_tiles * ITERS_PT;

    auto load_stage = [&](int it) {
        const int tile = cta + (it >> 5) * GRID_P;
        const int bn   = tile & 15;
        const int bm   = tile >> 4;
        const int ko   = (it & 31) * BK;
        const __half* Ag = g_x_h + (size_t)(bm * BM) * IN_F + ko;
        const __half* Bg = g_w_h + (size_t)(bn * BN) * IN_F + ko;
        const uint32_t sA = sbase + (it & 1) * STAGE_BYTES;
        const uint32_t sB = sA + A_STAGE_BYTES;
        #pragma unroll
        for (int t = 0; t < 4; t++) {
            int v = tid + t * NTHREADS;
            int r = v >> 4, c = v & 15;
            uint32_t off = (uint32_t)(r << 8) + (uint32_t)((c ^ (r & 7)) << 4);
            cp_async16(sA + off, Ag + (size_t)r * IN_F + c * 8);
        }
        #pragma unroll
        for (int t = 0; t < 8; t++) {
            int v = tid + t * NTHREADS;
            int r = v >> 4, c = v & 15;
            uint32_t off = (uint32_t)(r << 8) + (uint32_t)((c ^ (r & 7)) << 4);
            cp_async16(sB + off, Bg + (size_t)r * IN_F + c * 8);
        }
    };

    const int m_lane  = warp_m * 64 + (lane & 15);
    const int a_half  = lane >> 4;
    const int xa      = m_lane & 7;
    const int n_lane  = warp_n * 32 + (lane & 7) + ((lane >> 4) << 3);
    const int b_half  = (lane >> 3) & 1;
    const int xb      = n_lane & 7;

    float acc[4][4][4];
    #pragma unroll
    for (int i = 0; i < 4; i++)
        #pragma unroll
        for (int j = 0; j < 4; j++)
            #pragma unroll
            for (int k = 0; k < 4; k++) acc[i][j][k] = 0.0f;

    if (total_it == 0) return;
    load_stage(0);
    CP_COMMIT();

    for (int it = 0; it < total_it; it++) {
        CP_WAIT(0);
        __syncthreads();

        if (it + 1 < total_it) load_stage(it + 1);
        CP_COMMIT();

        const uint32_t sA = sbase + (it & 1) * STAGE_BYTES;
        const uint32_t sB = sA + A_STAGE_BYTES;
        const uint32_t aRow = sA + (uint32_t)(m_lane << 8);
        const uint32_t bRow = sB + (uint32_t)(n_lane << 8);

        #pragma unroll
        for (int kk = 0; kk < 8; kk++) {
            uint32_t a_frag[4][4];
            uint32_t b_frag[2][4];
            const uint32_t ac = (uint32_t)(((kk * 2 + a_half) ^ xa) << 4);
            const uint32_t bc = (uint32_t)(((kk * 2 + b_half) ^ xb) << 4);
            #pragma unroll
            for (int mt = 0; mt < 4; mt++)
                ldmatrix_x4(a_frag[mt], aRow + (uint32_t)(mt << 12) + ac);
            #pragma unroll
            for (int nt = 0; nt < 2; nt++)
                ldmatrix_x4(b_frag[nt], bRow + (uint32_t)(nt << 12) + bc);
            #pragma unroll
            for (int mt = 0; mt < 4; mt++) {
                #pragma unroll
                for (int nt = 0; nt < 2; nt++) {
                    mma16816(acc[mt][2 * nt],     a_frag[mt], &b_frag[nt][0]);
                    mma16816(acc[mt][2 * nt + 1], a_frag[mt], &b_frag[nt][2]);
                }
            }
        }

        if ((it & 31) == 31) {
            const int tile = cta + (it >> 5) * GRID_P;
            const int bn   = tile & 15;
            const int bm   = tile >> 4;
            const int row_base = bm * BM + warp_m * 64 + (lane >> 2);
            const int col_base = bn * BN + warp_n * 32 + 2 * (lane & 3);
            #pragma unroll
            for (int mt = 0; mt < 4; mt++) {
                const int r0 = row_base + mt * 16;
                #pragma unroll
                for (int n8 = 0; n8 < 4; n8++) {
                    const int col = col_base + n8 * 8;
                    float2 bv = *reinterpret_cast<const float2*>(bias + col);
                    float2 o0, o1;
                    o0.x = acc[mt][n8][0] + bv.x;
                    o0.y = acc[mt][n8][1] + bv.y;
                    o1.x = acc[mt][n8][2] + bv.x;
                    o1.y = acc[mt][n8][3] + bv.y;
                    *reinterpret_cast<float2*>(
                        C + (size_t)r0 * OUT_F + col) = o0;
                    *reinterpret_cast<float2*>(
                        C + (size_t)(r0 + 8) * OUT_F + col) = o1;
                    #pragma unroll
                    for (int k = 0; k < 4; k++) acc[mt][n8][k] = 0.0f;
                }
            }
        }
    }
}

// ---------------------------------------------------------------------------
// Launch
// ---------------------------------------------------------------------------
extern "C" void kernel_launch(void* const* d_in, const int* in_sizes, int n_in,
                              void* d_out, int out_size)
{
    const float* x              = (const float*)d_in[0];
    const float* weight         = (const float*)d_in[1];
    const float* bias           = (const float*)d_in[2];
    const float* channel_scales = (const float*)d_in[3];
    const float* theta          = (const float*)d_in[4];
    const float* q_scale        = (const float*)d_in[5];
    const float* q_zp           = (const float*)d_in[6];
    const int*   pairs          = (const int*)d_in[7];
    float* out = (float*)d_out;

    cudaFuncSetAttribute(gemm_mma_kernel,
                         cudaFuncAttributeMaxDynamicSharedMemorySize, GEMM_SMEM);

    dim3 tgrid(NGROUPS, OUT_F / ROWS_PB);
    transform_kernel<<<tgrid, 256>>>(weight, channel_scales, theta,
                                     q_scale, q_zp, pairs, x);

    gemm_mma_kernel<<<GRID_P, NTHREADS, GEMM_SMEM>>>(bias, out);
}

// round 14
// speedup vs baseline: 1.0869x; 1.0131x over previous
#include <cuda_runtime.h>
#include <cuda_fp16.h>
#include <cstdint>

#define IN_F     4096
#define OUT_F    4096
#define N_TOK    8192
#define GROUP    128
#define NGROUPS  (IN_F / GROUP)
#define N_STAGES 4
#define QMAXF    15.0f

// ---------------- scratch (device globals; no runtime allocation) ----------
__device__ __half g_w_h[(size_t)OUT_F * IN_F];
__device__ __half g_x_h[(size_t)N_TOK * IN_F];

// ---------------------------------------------------------------------------
// Kernel 1: fused weight transform + x->fp16 conversion.
// Transposed float2 tile wT2[channel][row_pair]: 64 rows/block as 32 pairs.
// Rotation LDS.64 is lane-consecutive -> conflict-free; instruction count per
// element halved vs R13. Block = (group g, 64 rows), 256 threads.
// ---------------------------------------------------------------------------
#define ROWS_PB 64
#define NPAIRS  (ROWS_PB / 2)                  // 32 row-pairs
#define RPAD    33
#define TBLOCKS (NGROUPS * (OUT_F / ROWS_PB))  // 2048
#define XCHUNK  ((size_t)N_TOK * IN_F / TBLOCKS)  // 16384 elems / block

__global__ __launch_bounds__(256) void transform_kernel(
    const float* __restrict__ weight,
    const float* __restrict__ channel_scales,
    const float* __restrict__ theta,
    const float* __restrict__ q_scale,
    const float* __restrict__ q_zp,
    const int*   __restrict__ pairs,
    const float* __restrict__ x)
{
    const int g    = blockIdx.x;               // 0..31
    const int row0 = blockIdx.y * ROWS_PB;     // 0..4032
    const int tid  = threadIdx.x;
    const int wrp  = tid >> 5;                 // 0..7
    const int lane = tid & 31;

    __shared__ float2 wT2[GROUP][RPAD];        // [channel][row_pair]
    __shared__ float cs_c[N_STAGES][64], cs_s[N_STAGES][64];
    __shared__ int   pi[N_STAGES][64], pj[N_STAGES][64];
    __shared__ float csc[GROUP];
    __shared__ float qs[ROWS_PB], qz[ROWS_PB];

    // ---- fused x -> fp16 conversion (independent DRAM stream) ----
    {
        const int blk = blockIdx.y * NGROUPS + blockIdx.x;   // 0..2047
        const float* xs = x + (size_t)blk * XCHUNK;
        __half* xd = g_x_h + (size_t)blk * XCHUNK;
        #pragma unroll
        for (int t = 0; t < (int)(XCHUNK / (256 * 8)); t++) {  // 8 iters
            size_t i = ((size_t)(t * 256 + tid)) * 8;
            float4 v0 = *reinterpret_cast<const float4*>(xs + i);
            float4 v1 = *reinterpret_cast<const float4*>(xs + i + 4);
            __half2 h[4];
            h[0] = __floats2half2_rn(v0.x, v0.y);
            h[1] = __floats2half2_rn(v0.z, v0.w);
            h[2] = __floats2half2_rn(v1.x, v1.y);
            h[3] = __floats2half2_rn(v1.z, v1.w);
            *reinterpret_cast<uint4*>(xd + i) =
                *reinterpret_cast<const uint4*>(h);
        }
    }

    // ---- tables ----
    if (tid < GROUP) csc[tid] = channel_scales[g * GROUP + tid];
    {
        int st = tid >> 6, p = tid & 63;       // 256 = 4 stages x 64 pairs
        float s, c;
        sincosf(theta[st * (IN_F / 2) + g * 64 + p], &s, &c);
        cs_c[st][p] = c;
        cs_s[st][p] = s;
        pi[st][p] = pairs[st * IN_F + g * GROUP + 2 * p];
        pj[st][p] = pairs[st * IN_F + g * GROUP + 2 * p + 1];
    }
    if (tid < ROWS_PB) {
        int gi = (row0 + tid) * NGROUPS + g;
        qs[tid] = fminf(fmaxf(q_scale[gi], 1e-5f), 1e5f);
        qz[tid] = fminf(fmaxf(-rintf(q_zp[gi]), 0.0f), QMAXF);
    }
    __syncthreads();

    // ---- transposed load + channel scale (two rows per float2) ----
    const int lr2 = wrp * 4 + (lane >> 3);     // row-pair index 0..31
    const int rowa = row0 + 2 * lr2;
    #pragma unroll
    for (int it = 0; it < 4; it++) {
        int c4 = ((lane & 7) + it * 8) * 4;
        float4 va = *reinterpret_cast<const float4*>(
            weight + (size_t)rowa * IN_F + g * GROUP + c4);
        float4 vb = *reinterpret_cast<const float4*>(
            weight + (size_t)(rowa + 1) * IN_F + g * GROUP + c4);
        wT2[c4 + 0][lr2] = make_float2(va.x * csc[c4 + 0], vb.x * csc[c4 + 0]);
        wT2[c4 + 1][lr2] = make_float2(va.y * csc[c4 + 1], vb.y * csc[c4 + 1]);
        wT2[c4 + 2][lr2] = make_float2(va.z * csc[c4 + 2], vb.z * csc[c4 + 2]);
        wT2[c4 + 3][lr2] = make_float2(va.w * csc[c4 + 3], vb.w * csc[c4 + 3]);
    }
    __syncthreads();

    // ---- forward rotations: lane = row-pair, conflict-free LDS.64 ----
    #pragma unroll
    for (int st = 0; st < N_STAGES; st++) {
        #pragma unroll
        for (int t = 0; t < 8; t++) {
            int p = wrp + t * 8;
            float c = cs_c[st][p], s = cs_s[st][p];
            int i = pi[st][p], j = pj[st][p];
            float2 xi = wT2[i][lane], xj = wT2[j][lane];
            wT2[i][lane] = make_float2( xi.x * c + xj.x * s,
                                        xi.y * c + xj.y * s);
            wT2[j][lane] = make_float2(-xi.x * s + xj.x * c,
                                       -xi.y * s + xj.y * c);
        }
        __syncthreads();
    }

    // ---- quant-dequant: lane owns rows (2*lane, 2*lane+1) ----
    {
        float sa = qs[2 * lane],     za = qz[2 * lane];
        float sb = qs[2 * lane + 1], zb = qz[2 * lane + 1];
        #pragma unroll
        for (int t = 0; t < 16; t++) {
            int c = wrp + t * 8;
            float2 v = wT2[c][lane];
            float qa = rintf(v.x / sa) + za;
            qa = fminf(fmaxf(qa, 0.0f), QMAXF);
            float qb = rintf(v.y / sb) + zb;
            qb = fminf(fmaxf(qb, 0.0f), QMAXF);
            wT2[c][lane] = make_float2((qa - za) * sa, (qb - zb) * sb);
        }
    }
    __syncthreads();

    // ---- inverse rotations ----
    #pragma unroll
    for (int st = N_STAGES - 1; st >= 0; st--) {
        #pragma unroll
        for (int t = 0; t < 8; t++) {
            int p = wrp + t * 8;
            float c = cs_c[st][p], s = cs_s[st][p];
            int i = pi[st][p], j = pj[st][p];
            float2 xi = wT2[i][lane], xj = wT2[j][lane];
            wT2[i][lane] = make_float2(xi.x * c - xj.x * s,
                                       xi.y * c - xj.y * s);
            wT2[j][lane] = make_float2(xi.x * s + xj.x * c,
                                       xi.y * s + xj.y * c);
        }
        __syncthreads();
    }

    // ---- unscale + fp16 store (8B stores, both rows) ----
    #pragma unroll
    for (int it = 0; it < 4; it++) {
        int c4 = ((lane & 7) + it * 8) * 4;
        float2 u0 = wT2[c4 + 0][lr2];
        float2 u1 = wT2[c4 + 1][lr2];
        float2 u2 = wT2[c4 + 2][lr2];
        float2 u3 = wT2[c4 + 3][lr2];
        float i0 = csc[c4 + 0], i1 = csc[c4 + 1];
        float i2 = csc[c4 + 2], i3 = csc[c4 + 3];
        __half2 ha[2], hb[2];
        ha[0] = __floats2half2_rn(u0.x / i0, u1.x / i1);
        ha[1] = __floats2half2_rn(u2.x / i2, u3.x / i3);
        hb[0] = __floats2half2_rn(u0.y / i0, u1.y / i1);
        hb[1] = __floats2half2_rn(u2.y / i2, u3.y / i3);
        *reinterpret_cast<uint2*>(
            g_w_h + (size_t)rowa * IN_F + g * GROUP + c4) =
            *reinterpret_cast<const uint2*>(ha);
        *reinterpret_cast<uint2*>(
            g_w_h + (size_t)(rowa + 1) * IN_F + g * GROUP + c4) =
            *reinterpret_cast<const uint2*>(hb);
    }
}

// ---------------------------------------------------------------------------
// Kernel 2: PERSISTENT fp16 mma.sync GEMM (R12/R13, measured ~615us; parked).
// ---------------------------------------------------------------------------
#define BM 128
#define BN 256
#define BK 128
#define NTHREADS 512
#define GRID_P   148
#define NTILES   ((OUT_F / BN) * (N_TOK / BM))            // 1024
#define ITERS_PT (IN_F / BK)                              // 32
#define A_STAGE_BYTES (BM * BK * 2)                       // 32768
#define B_STAGE_BYTES (BN * BK * 2)                       // 65536
#define STAGE_BYTES   (A_STAGE_BYTES + B_STAGE_BYTES)     // 98304
#define GEMM_SMEM     (2 * STAGE_BYTES)                   // 196608

__device__ __forceinline__ uint32_t smem_u32(const void* p) {
    uint32_t a;
    asm("{ .reg .u64 t; cvta.to.shared.u64 t, %1; cvt.u32.u64 %0, t; }"
        : "=r"(a) : "l"(p));
    return a;
}
__device__ __forceinline__ void cp_async16(uint32_t saddr, const void* gptr) {
    asm volatile("cp.async.cg.shared.global [%0], [%1], 16;"
                 :: "r"(saddr), "l"(gptr));
}
#define CP_COMMIT() asm volatile("cp.async.commit_group;" ::: "memory")
#define CP_WAIT(n)  asm volatile("cp.async.wait_group %0;" :: "n"(n) : "memory")

__device__ __forceinline__ void ldmatrix_x4(uint32_t* r, uint32_t addr) {
    asm volatile("ldmatrix.sync.aligned.m8n8.x4.shared.b16 {%0,%1,%2,%3}, [%4];"
                 : "=r"(r[0]), "=r"(r[1]), "=r"(r[2]), "=r"(r[3]) : "r"(addr));
}
__device__ __forceinline__ void mma16816(float* c, const uint32_t* a,
                                         const uint32_t* b) {
    asm volatile("mma.sync.aligned.m16n8k16.row.col.f32.f16.f16.f32 "
                 "{%0,%1,%2,%3}, {%4,%5,%6,%7}, {%8,%9}, {%0,%1,%2,%3};"
                 : "+f"(c[0]), "+f"(c[1]), "+f"(c[2]), "+f"(c[3])
                 : "r"(a[0]), "r"(a[1]), "r"(a[2]), "r"(a[3]),
                   "r"(b[0]), "r"(b[1]));
}

__global__ __launch_bounds__(NTHREADS, 1) void gemm_mma_kernel(
    const float* __restrict__ bias, float* __restrict__ C)
{
    extern __shared__ char smem[];
    const uint32_t sbase = smem_u32(smem);
    const int tid  = threadIdx.x;
    const int wid  = tid >> 5;
    const int lane = tid & 31;
    const int cta  = blockIdx.x;
    const int warp_m = wid >> 3;
    const int warp_n = wid & 7;

    const int my_tiles = (NTILES - cta + GRID_P - 1) / GRID_P;
    const int total_it = my_tiles * ITERS_PT;

    auto load_stage = [&](int it) {
        const int tile = cta + (it >> 5) * GRID_P;
        const int bn   = tile & 15;
        const int bm   = tile >> 4;
        const int ko   = (it & 31) * BK;
        const __half* Ag = g_x_h + (size_t)(bm * BM) * IN_F + ko;
        const __half* Bg = g_w_h + (size_t)(bn * BN) * IN_F + ko;
        const uint32_t sA = sbase + (it & 1) * STAGE_BYTES;
        const uint32_t sB = sA + A_STAGE_BYTES;
        #pragma unroll
        for (int t = 0; t < 4; t++) {
            int v = tid + t * NTHREADS;
            int r = v >> 4, c = v & 15;
            uint32_t off = (uint32_t)(r << 8) + (uint32_t)((c ^ (r & 7)) << 4);
            cp_async16(sA + off, Ag + (size_t)r * IN_F + c * 8);
        }
        #pragma unroll
        for (int t = 0; t < 8; t++) {
            int v = tid + t * NTHREADS;
            int r = v >> 4, c = v & 15;
            uint32_t off = (uint32_t)(r << 8) + (uint32_t)((c ^ (r & 7)) << 4);
            cp_async16(sB + off, Bg + (size_t)r * IN_F + c * 8);
        }
    };

    const int m_lane  = warp_m * 64 + (lane & 15);
    const int a_half  = lane >> 4;
    const int xa      = m_lane & 7;
    const int n_lane  = warp_n * 32 + (lane & 7) + ((lane >> 4) << 3);
    const int b_half  = (lane >> 3) & 1;
    const int xb      = n_lane & 7;

    float acc[4][4][4];
    #pragma unroll
    for (int i = 0; i < 4; i++)
        #pragma unroll
        for (int j = 0; j < 4; j++)
            #pragma unroll
            for (int k = 0; k < 4; k++) acc[i][j][k] = 0.0f;

    if (total_it == 0) return;
    load_stage(0);
    CP_COMMIT();

    for (int it = 0; it < total_it; it++) {
        CP_WAIT(0);
        __syncthreads();

        if (it + 1 < total_it) load_stage(it + 1);
        CP_COMMIT();

        const uint32_t sA = sbase + (it & 1) * STAGE_BYTES;
        const uint32_t sB = sA + A_STAGE_BYTES;
        const uint32_t aRow = sA + (uint32_t)(m_lane << 8);
        const uint32_t bRow = sB + (uint32_t)(n_lane << 8);

        #pragma unroll
        for (int kk = 0; kk < 8; kk++) {
            uint32_t a_frag[4][4];
            uint32_t b_frag[2][4];
            const uint32_t ac = (uint32_t)(((kk * 2 + a_half) ^ xa) << 4);
            const uint32_t bc = (uint32_t)(((kk * 2 + b_half) ^ xb) << 4);
            #pragma unroll
            for (int mt = 0; mt < 4; mt++)
                ldmatrix_x4(a_frag[mt], aRow + (uint32_t)(mt << 12) + ac);
            #pragma unroll
            for (int nt = 0; nt < 2; nt++)
                ldmatrix_x4(b_frag[nt], bRow + (uint32_t)(nt << 12) + bc);
            #pragma unroll
            for (int mt = 0; mt < 4; mt++) {
                #pragma unroll
                for (int nt = 0; nt < 2; nt++) {
                    mma16816(acc[mt][2 * nt],     a_frag[mt], &b_frag[nt][0]);
                    mma16816(acc[mt][2 * nt + 1], a_frag[mt], &b_frag[nt][2]);
                }
            }
        }

        if ((it & 31) == 31) {
            const int tile = cta + (it >> 5) * GRID_P;
            const int bn   = tile & 15;
            const int bm   = tile >> 4;
            const int row_base = bm * BM + warp_m * 64 + (lane >> 2);
            const int col_base = bn * BN + warp_n * 32 + 2 * (lane & 3);
            #pragma unroll
            for (int mt = 0; mt < 4; mt++) {
                const int r0 = row_base + mt * 16;
                #pragma unroll
                for (int n8 = 0; n8 < 4; n8++) {
                    const int col = col_base + n8 * 8;
                    float2 bv = *reinterpret_cast<const float2*>(bias + col);
                    float2 o0, o1;
                    o0.x = acc[mt][n8][0] + bv.x;
                    o0.y = acc[mt][n8][1] + bv.y;
                    o1.x = acc[mt][n8][2] + bv.x;
                    o1.y = acc[mt][n8][3] + bv.y;
                    *reinterpret_cast<float2*>(
                        C + (size_t)r0 * OUT_F + col) = o0;
                    *reinterpret_cast<float2*>(
                        C + (size_t)(r0 + 8) * OUT_F + col) = o1;
                    #pragma unroll
                    for (int k = 0; k < 4; k++) acc[mt][n8][k] = 0.0f;
                }
            }
        }
    }
}

// ---------------------------------------------------------------------------
// Launch
// ---------------------------------------------------------------------------
extern "C" void kernel_launch(void* const* d_in, const int* in_sizes, int n_in,
                              void* d_out, int out_size)
{
    const float* x              = (const float*)d_in[0];
    const float* weight         = (const float*)d_in[1];
    const float* bias           = (const float*)d_in[2];
    const float* channel_scales = (const float*)d_in[3];
    const float* theta          = (const float*)d_in[4];
    const float* q_scale        = (const float*)d_in[5];
    const float* q_zp           = (const float*)d_in[6];
    const int*   pairs          = (const int*)d_in[7];
    float* out = (float*)d_out;

    cudaFuncSetAttribute(gemm_mma_kernel,
                         cudaFuncAttributeMaxDynamicSharedMemorySize, GEMM_SMEM);

    dim3 tgrid(NGROUPS, OUT_F / ROWS_PB);
    transform_kernel<<<tgrid, 256>>>(weight, channel_scales, theta,
                                     q_scale, q_zp, pairs, x);

    gemm_mma_kernel<<<GRID_P, NTHREADS, GEMM_SMEM>>>(bias, out);
}